// round 1
// baseline (speedup 1.0000x reference)
#include <cuda_runtime.h>

// Input:  image [256, 384, 384] float32  (i, j, c')
// Output: out   [1, 384, 320, 512] float32  (j, a, c)
//
// out[j,a,c] = lerp over i (256->320, half-pixel, clamp0) of
//              lerp over c' (384->512, half-pixel, clamp0) of image[i,j,c']

#define D0 256
#define D1 384
#define D2 384
#define S0 320
#define S1 384
#define S2 512

__global__ __launch_bounds__(512)
void resize3d_kernel(const float* __restrict__ in, float* __restrict__ out) {
    const int c = threadIdx.x;       // 0..511  (output fast dim)
    const int a = blockIdx.x;        // 0..319  (resized dim0, fastest grid dim for L2 reuse)
    const int j = blockIdx.y;        // 0..383  (pass-through dim)

    // --- c (last axis) interpolation: 384 -> 512, scale 0.75 ---
    // src = max((c+0.5)*0.75 - 0.5, 0)
    float sc = fmaxf((c + 0.5f) * 0.75f - 0.5f, 0.0f);
    int   c0 = (int)sc;              // sc >= 0, floor == trunc
    float wc = sc - (float)c0;
    int   c1 = min(c0 + 1, D2 - 1);

    // --- a (dim0) interpolation: 256 -> 320, scale 0.8 ---
    float sa = fmaxf((a + 0.5f) * 0.8f - 0.5f, 0.0f);
    int   i0 = (int)sa;
    float wa = sa - (float)i0;
    int   i1 = min(i0 + 1, D0 - 1);

    const float* __restrict__ r0 = in + ((size_t)i0 * D1 + j) * D2;
    const float* __restrict__ r1 = in + ((size_t)i1 * D1 + j) * D2;

    float a00 = __ldg(r0 + c0);
    float a01 = __ldg(r0 + c1);
    float a10 = __ldg(r1 + c0);
    float a11 = __ldg(r1 + c1);

    float v0 = a00 * (1.0f - wc) + a01 * wc;
    float v1 = a10 * (1.0f - wc) + a11 * wc;
    float v  = v0 * (1.0f - wa) + v1 * wa;

    out[((size_t)j * S0 + a) * S2 + c] = v;
}

extern "C" void kernel_launch(void* const* d_in, const int* in_sizes, int n_in,
                              void* d_out, int out_size) {
    (void)in_sizes; (void)n_in; (void)out_size;
    const float* in = (const float*)d_in[0];
    float* out = (float*)d_out;

    dim3 grid(S0, S1, 1);   // a fastest-varying -> consecutive blocks share input rows in L2
    dim3 block(S2, 1, 1);
    resize3d_kernel<<<grid, block>>>(in, out);
}

// round 2
// speedup vs baseline: 2.9791x; 2.9791x over previous
#include <cuda_runtime.h>

// Input:  image [256, 384, 384] float32   (i, j, c')
// Output: out   [1, 384, 320, 512] float32 (j, a, c)
//
// Separable bilinear with rational scales:
//   c: 384 -> 512 (x4/3): outputs 4k..4k+3 <- inputs 3k-1..3k+3,
//      weights {0.875, 0.625, 0.375, 0.125}
//   a: 256 -> 320 (x5/4): outputs 5m..5m+4 <- input rows 4m-1..4m+4,
//      weights {0.9, 0.7, 0.5, 0.3, 0.1}, consecutive row pairs
// Boundary clamps degenerate to x[i]==x[i+1], making the fixed weights valid
// everywhere.

#define D0 256
#define D1 384
#define D2 384
#define S0 320
#define S1 384
#define S2 512

__global__ __launch_bounds__(128)
void resize3d_kernel(const float* __restrict__ in, float* __restrict__ out) {
    const int k = threadIdx.x;   // c-group 0..127  -> output cols 4k..4k+3
    const int m = blockIdx.x;    // a-group 0..63   -> output rows 5m..5m+4
    const int j = blockIdx.y;    // 0..383 pass-through dim

    // Column taps (clamped). col[t] = clamp(3k-1+t, 0, 383)
    int col0 = max(3 * k - 1, 0);
    int col1 = 3 * k;
    int col2 = 3 * k + 1;
    int col3 = 3 * k + 2;
    int col4 = min(3 * k + 3, D2 - 1);

    const float* base = in + (size_t)j * D2;        // + i * D1*D2
    const size_t rowstride = (size_t)D1 * D2;

    float prev0, prev1, prev2, prev3;

    // c-lerp one input row into a 4-vector
    auto loadrow = [&](int i, float& l0, float& l1, float& l2, float& l3) {
        const float* r = base + (size_t)i * rowstride;
        float x0 = __ldg(r + col0);
        float x1 = __ldg(r + col1);
        float x2 = __ldg(r + col2);
        float x3 = __ldg(r + col3);
        float x4 = __ldg(r + col4);
        l0 = x0 + 0.875f * (x1 - x0);
        l1 = x1 + 0.625f * (x2 - x1);
        l2 = x2 + 0.375f * (x3 - x2);
        l3 = x3 + 0.125f * (x4 - x3);
    };

    loadrow(max(4 * m - 1, 0), prev0, prev1, prev2, prev3);

    float4* op = (float4*)(out + ((size_t)j * S0 + 5 * m) * S2 + 4 * k);
    const float wa[5] = {0.9f, 0.7f, 0.5f, 0.3f, 0.1f};

    #pragma unroll
    for (int s = 0; s < 5; ++s) {
        float c0, c1, c2, c3;
        loadrow(min(4 * m + s, D0 - 1), c0, c1, c2, c3);
        float w = wa[s];
        float4 o;
        o.x = prev0 + w * (c0 - prev0);
        o.y = prev1 + w * (c1 - prev1);
        o.z = prev2 + w * (c2 - prev2);
        o.w = prev3 + w * (c3 - prev3);
        *op = o;
        op += S2 / 4;
        prev0 = c0; prev1 = c1; prev2 = c2; prev3 = c3;
    }
}

extern "C" void kernel_launch(void* const* d_in, const int* in_sizes, int n_in,
                              void* d_out, int out_size) {
    (void)in_sizes; (void)n_in; (void)out_size;
    const float* in = (const float*)d_in[0];
    float* out = (float*)d_out;

    dim3 grid(S0 / 5, S1, 1);   // (a-groups, j)
    dim3 block(128, 1, 1);      // one c-group per thread
    resize3d_kernel<<<grid, block>>>(in, out);
}